// round 11
// baseline (speedup 1.0000x reference)
#include <cuda_runtime.h>
#include <cuda_bf16.h>
#include <cstdint>
#include <cstddef>

// Problem constants
#define BB   64
#define NN   4096
#define DD   256
#define CC   20
#define SPL  16          // N-splits per batch (256 tokens per block)
#define TT   64          // tokens per sub-chunk
#define NSC  4           // sub-chunks per block
#define NTHR 256

// smem layout (byte offsets). Row strides % 128B == 16B -> 4-bank shift/row,
// conflict-free ldmatrix phases.
#define XR   528         // X row stride bytes: (256+8)*2
#define CR   528         // codebook row stride bytes
#define PR   144         // P row stride bytes: (64+8)*2
#define SSW  72          // sS row stride in words (64+8)

#define XHI   0          // bf16 [64][264]
#define XLO   33792
#define CHI   67584      // bf16 [24 rows, 20 valid][264]
#define CLO   80256
#define PHI   92928      // bf16 [32 rows, 20 valid][72]
#define PLO   97536
#define SSO   102144     // f32 [24][72]
#define STAT  109056     // sM[32], sSum[32], sScale[32]
#define STAGE 109568     // raw fp32 staging [64][256] = 65536 B
#define SMEM_BYTES 175104

#define DXL  (XLO - XHI)
#define DCL  (CLO - CHI)
#define DPL  (PLO - PHI)

// Scratch (device globals: no allocation allowed)
__device__ float g_acc[BB * SPL * CC * DD];   // 21 MB
__device__ float g_m[BB * SPL * CC];
__device__ float g_s[BB * SPL * CC];
__device__ uint32_t g_cbh[CC * DD / 2];       // codebook bf16 hi (packed pairs)
__device__ uint32_t g_cbl[CC * DD / 2];       // codebook bf16 lo

// ---------------- helpers ----------------
__device__ __forceinline__ uint32_t smem_u32(const void* p) {
    uint32_t a;
    asm("{ .reg .u64 t; cvta.to.shared.u64 t, %1; cvt.u32.u64 %0, t; }" : "=r"(a) : "l"(p));
    return a;
}
__device__ __forceinline__ void cp_async16(uint32_t dst, const void* src) {
    asm volatile("cp.async.cg.shared.global [%0], [%1], 16;" :: "r"(dst), "l"(src));
}
#define CP_COMMIT() asm volatile("cp.async.commit_group;" ::: "memory")
#define CP_WAIT0()  asm volatile("cp.async.wait_group 0;" ::: "memory")

__device__ __forceinline__ void ldsm4(uint32_t* r, uint32_t a) {
    asm volatile("ldmatrix.sync.aligned.m8n8.x4.shared.b16 {%0,%1,%2,%3}, [%4];"
        : "=r"(r[0]), "=r"(r[1]), "=r"(r[2]), "=r"(r[3]) : "r"(a));
}
__device__ __forceinline__ void ldsm4t(uint32_t* r, uint32_t a) {
    asm volatile("ldmatrix.sync.aligned.m8n8.x4.trans.shared.b16 {%0,%1,%2,%3}, [%4];"
        : "=r"(r[0]), "=r"(r[1]), "=r"(r[2]), "=r"(r[3]) : "r"(a));
}
__device__ __forceinline__ void ldsm2(uint32_t* r, uint32_t a) {
    asm volatile("ldmatrix.sync.aligned.m8n8.x2.shared.b16 {%0,%1}, [%2];"
        : "=r"(r[0]), "=r"(r[1]) : "r"(a));
}
__device__ __forceinline__ void mmabf(float* d, const uint32_t* a, const uint32_t* b) {
    asm volatile("mma.sync.aligned.m16n8k16.row.col.f32.bf16.bf16.f32 "
        "{%0,%1,%2,%3}, {%4,%5,%6,%7}, {%8,%9}, {%0,%1,%2,%3};"
        : "+f"(d[0]), "+f"(d[1]), "+f"(d[2]), "+f"(d[3])
        : "r"(a[0]), "r"(a[1]), "r"(a[2]), "r"(a[3]), "r"(b[0]), "r"(b[1]));
}
__device__ __forceinline__ void cvt4(float4 v, uint32_t& h01, uint32_t& h23,
                                     uint32_t& l01, uint32_t& l23) {
    __nv_bfloat162 h0 = __floats2bfloat162_rn(v.x, v.y);
    __nv_bfloat162 h1 = __floats2bfloat162_rn(v.z, v.w);
    float2 f0 = __bfloat1622float2(h0);
    float2 f1 = __bfloat1622float2(h1);
    __nv_bfloat162 l0 = __floats2bfloat162_rn(v.x - f0.x, v.y - f0.y);
    __nv_bfloat162 l1 = __floats2bfloat162_rn(v.z - f1.x, v.w - f1.y);
    h01 = *reinterpret_cast<uint32_t*>(&h0); h23 = *reinterpret_cast<uint32_t*>(&h1);
    l01 = *reinterpret_cast<uint32_t*>(&l0); l23 = *reinterpret_cast<uint32_t*>(&l1);
}

// ---- prep: codebook fp32 -> bf16 hi/lo once per call ----
__global__ void __launch_bounds__(256)
prep_kernel(const float* __restrict__ cb)
{
    const int tid = threadIdx.x;
    for (int i = tid; i < CC * DD / 4; i += 256) {
        const float4 v = reinterpret_cast<const float4*>(cb)[i];
        uint32_t h01, h23, l01, l23;
        cvt4(v, h01, h23, l01, l23);
        g_cbh[2 * i] = h01; g_cbh[2 * i + 1] = h23;
        g_cbl[2 * i] = l01; g_cbl[2 * i + 1] = l23;
    }
}

__global__ void noop_kernel() {}

__global__ void __launch_bounds__(NTHR, 1)
attn_main_kernel(const float* __restrict__ pe)
{
    extern __shared__ char smem[];
    const uint32_t sb = smem_u32(smem);
    const int tid = threadIdx.x;
    const int lane = tid & 31;
    const int wid  = tid >> 5;        // 0..7
    const int sp = blockIdx.x;
    const int b  = blockIdx.y;

    float* sM     = reinterpret_cast<float*>(smem + STAT);
    float* sSum   = sM + 32;
    float* sScale = sSum + 32;
    float* stage  = reinterpret_cast<float*>(smem + STAGE);

    const float* Xb = pe + ((size_t)b * NN + (size_t)sp * (NSC * TT)) * DD;

    // ---- prologue: cp.async sub-chunk 0 -> stage ----
#pragma unroll
    for (int i = 0; i < 16; i++) {
        const int idx = i * NTHR + tid;     // 4096 float4
        cp_async16(sb + STAGE + idx * 16, Xb + idx * 4);
    }
    CP_COMMIT();

    // ---- load prequantized codebook -> Chi/Clo [20 valid rows][264] ----
#pragma unroll
    for (int it = 0; it < 10; it++) {
        const int i = it * NTHR + tid;      // 2560 pairs
        const int c = i >> 7, dp = i & 127;
        *reinterpret_cast<uint32_t*>(smem + CHI + c * CR + dp * 4) = g_cbh[i];
        *reinterpret_cast<uint32_t*>(smem + CLO + c * CR + dp * 4) = g_cbl[i];
    }
    if (tid < 32) { sM[tid] = -1e30f; sSum[tid] = 0.0f; sScale[tid] = 0.0f; }

    // ---- convert sub-chunk 0: stage -> Xhi/Xlo ----
    CP_WAIT0();
    __syncthreads();
#pragma unroll
    for (int i = 0; i < 16; i++) {
        const int idx = i * NTHR + tid;     // 4096 quads = 64 tok x 64 quads
        const int t = idx >> 6, q = idx & 63;
        const float4 v = *reinterpret_cast<const float4*>(stage + idx * 4);
        uint32_t h01, h23, l01, l23;
        cvt4(v, h01, h23, l01, l23);
        *reinterpret_cast<uint2*>(smem + XHI + t * XR + q * 8) = make_uint2(h01, h23);
        *reinterpret_cast<uint2*>(smem + XLO + t * XR + q * 8) = make_uint2(l01, l23);
    }
    __syncthreads();

    const int sub = lane >> 3, lr = lane & 7;
    const int g = lane >> 2, i2 = (lane & 3) * 2;
    float* sS = reinterpret_cast<float*>(smem + SSO);

    // GEMM2 persistent accumulators (rescaled online each sub-chunk)
    float oacc[8][4] = {};
    const int mt2 = wid & 1;
    const int n0  = (wid >> 1) * 64;
    const int cA  = mt2 * 16 + g;
    const int cB  = cA + 8;

    for (int sc = 0; sc < NSC; sc++) {
        // ---- issue cp.async prefetch of next sub-chunk into stage ----
        if (sc + 1 < NSC) {
            const float* Xn = Xb + (size_t)(sc + 1) * TT * DD;
#pragma unroll
            for (int i = 0; i < 16; i++) {
                const int idx = i * NTHR + tid;
                cp_async16(sb + STAGE + idx * 16, Xn + idx * 4);
            }
            CP_COMMIT();
        }

        // ---- GEMM1: S[64t x 20c] = X . C^T (3-term bf16 split) ----
        {
            const int mt = wid & 3;
            const int ng = wid >> 2;
            const int m0 = mt * 16;
            const uint32_t aoff = sb + XHI + (uint32_t)(m0 + lr + (sub & 1) * 8) * XR + (sub >> 1) * 16;
            if (ng == 0) {
                const uint32_t boff = sb + CHI + (uint32_t)((sub >> 1) * 8 + lr) * CR + (sub & 1) * 16;
                float acc[2][4] = {};
#pragma unroll 4
                for (int k = 0; k < 16; k++) {
                    uint32_t ah[4], al[4], bh[4], bl[4];
                    ldsm4(ah, aoff + k * 32);
                    ldsm4(al, aoff + DXL + k * 32);
                    ldsm4(bh, boff + k * 32);
                    ldsm4(bl, boff + DCL + k * 32);
                    mmabf(acc[0], ah, bh + 0); mmabf(acc[0], ah, bl + 0); mmabf(acc[0], al, bh + 0);
                    mmabf(acc[1], ah, bh + 2); mmabf(acc[1], ah, bl + 2); mmabf(acc[1], al, bh + 2);
                }
#pragma unroll
                for (int n = 0; n < 2; n++) {
                    const int c0 = n * 8 + i2;
                    sS[c0 * SSW + m0 + g]           = acc[n][0];
                    sS[(c0 + 1) * SSW + m0 + g]     = acc[n][1];
                    sS[c0 * SSW + m0 + g + 8]       = acc[n][2];
                    sS[(c0 + 1) * SSW + m0 + g + 8] = acc[n][3];
                }
            } else {
                const uint32_t boff = sb + CHI + (uint32_t)(16 + lr) * CR + (uint32_t)(sub & 1) * 16;
                float acc[4] = {};
#pragma unroll 4
                for (int k = 0; k < 16; k++) {
                    uint32_t ah[4], al[4], bh[2], bl[2];
                    ldsm4(ah, aoff + k * 32);
                    ldsm4(al, aoff + DXL + k * 32);
                    ldsm2(bh, boff + k * 32);
                    ldsm2(bl, boff + DCL + k * 32);
                    mmabf(acc, ah, bh); mmabf(acc, ah, bl); mmabf(acc, al, bh);
                }
                const int c0 = 16 + i2;
                if (c0 < CC) {
                    sS[c0 * SSW + m0 + g]           = acc[0];
                    sS[(c0 + 1) * SSW + m0 + g]     = acc[1];
                    sS[c0 * SSW + m0 + g + 8]       = acc[2];
                    sS[(c0 + 1) * SSW + m0 + g + 8] = acc[3];
                }
            }
        }
        __syncthreads();

        // ---- online softmax over this sub-chunk; write P hi/lo [c][t] ----
        for (int c = wid; c < CC; c += 8) {
            float v[2];
#pragma unroll
            for (int r = 0; r < 2; r++) v[r] = sS[c * SSW + lane + 32 * r];
            float mx = fmaxf(v[0], v[1]);
#pragma unroll
            for (int off = 16; off > 0; off >>= 1)
                mx = fmaxf(mx, __shfl_xor_sync(0xffffffffu, mx, off));
            const float mold = sM[c];
            const float mnew = fmaxf(mold, mx);
            float p[2], psum = 0.0f;
#pragma unroll
            for (int r = 0; r < 2; r++) { p[r] = __expf(v[r] - mnew); psum += p[r]; }
#pragma unroll
            for (int off = 16; off > 0; off >>= 1)
                psum += __shfl_xor_sync(0xffffffffu, psum, off);
#pragma unroll
            for (int r = 0; r < 2; r++) {
                const int t = lane + 32 * r;
                __nv_bfloat16 hb = __float2bfloat16(p[r]);
                const float hf = __bfloat162float(hb);
                __nv_bfloat16 lb = __float2bfloat16(p[r] - hf);
                *reinterpret_cast<unsigned short*>(smem + PHI + c * PR + t * 2) =
                    *reinterpret_cast<unsigned short*>(&hb);
                *reinterpret_cast<unsigned short*>(smem + PLO + c * PR + t * 2) =
                    *reinterpret_cast<unsigned short*>(&lb);
            }
            if (lane == 0) {
                sScale[c] = __expf(mold - mnew);
                sSum[c]   = sSum[c] * sScale[c] + psum;
                sM[c]     = mnew;
            }
        }
        __syncthreads();

        // ---- GEMM2: rescale oacc, then accumulate P . X for this sub-chunk ----
        {
            const float fA = sScale[cA];   // c >= 20 lanes: acc never written out
            const float fB = sScale[cB];
#pragma unroll
            for (int n = 0; n < 8; n++) {
                oacc[n][0] *= fA; oacc[n][1] *= fA;
                oacc[n][2] *= fB; oacc[n][3] *= fB;
            }
            const uint32_t aoff = sb + PHI + (uint32_t)(mt2 * 16 + lr + (sub & 1) * 8) * PR + (sub >> 1) * 16;
            const uint32_t boff = sb + XHI + (uint32_t)((sub & 1) * 8 + lr) * XR
                                  + (uint32_t)(n0 + (sub >> 1) * 8) * 2;
#pragma unroll
            for (int k = 0; k < 4; k++) {
                uint32_t ah[4], al[4];
                ldsm4(ah, aoff + k * 32);
                ldsm4(al, aoff + DPL + k * 32);
#pragma unroll
                for (int np = 0; np < 4; np++) {
                    uint32_t bh[4], bl[4];
                    const uint32_t ba = boff + (uint32_t)k * (16 * XR) + np * 32;
                    ldsm4t(bh, ba);
                    ldsm4t(bl, ba + DXL);
                    float* a0 = oacc[2 * np];
                    float* a1 = oacc[2 * np + 1];
                    mmabf(a0, ah, bh + 0); mmabf(a0, ah, bl + 0); mmabf(a0, al, bh + 0);
                    mmabf(a1, ah, bh + 2); mmabf(a1, ah, bl + 2); mmabf(a1, al, bh + 2);
                }
            }
        }

        // ---- convert staged fp32 -> X bf16 tiles for next sub-chunk ----
        if (sc + 1 < NSC) {
            CP_WAIT0();
            __syncthreads();   // GEMM2 X reads done AND stage data landed
#pragma unroll
            for (int i = 0; i < 16; i++) {
                const int idx = i * NTHR + tid;
                const int t = idx >> 6, q = idx & 63;
                const float4 v = *reinterpret_cast<const float4*>(stage + idx * 4);
                uint32_t h01, h23, l01, l23;
                cvt4(v, h01, h23, l01, l23);
                *reinterpret_cast<uint2*>(smem + XHI + t * XR + q * 8) = make_uint2(h01, h23);
                *reinterpret_cast<uint2*>(smem + XLO + t * XR + q * 8) = make_uint2(l01, l23);
            }
            __syncthreads();
        }
    }

    // ---- epilogue: write split partials ----
    {
        float* ga = g_acc + (size_t)(b * SPL + sp) * CC * DD;
#pragma unroll
        for (int n = 0; n < 8; n++) {
            const int d = n0 + n * 8 + i2;
            if (cA < CC)
                *reinterpret_cast<float2*>(&ga[cA * DD + d]) = make_float2(oacc[n][0], oacc[n][1]);
            if (cB < CC)
                *reinterpret_cast<float2*>(&ga[cB * DD + d]) = make_float2(oacc[n][2], oacc[n][3]);
        }
    }
    __syncthreads();
    if (tid < CC) {
        g_m[(b * SPL + sp) * CC + tid] = sM[tid];
        g_s[(b * SPL + sp) * CC + tid] = sSum[tid];
    }
}

// ---- combine: one block per (b, c) row; 256 threads = one d each ----
__global__ void __launch_bounds__(256)
attn_combine_kernel(float* __restrict__ out)
{
    __shared__ float coef[SPL];
    __shared__ float shm[SPL], shs[SPL];
    const int c = blockIdx.x;
    const int b = blockIdx.y;
    const int tid = threadIdx.x;

    if (tid < SPL) {
        shm[tid] = g_m[(b * SPL + tid) * CC + c];
        shs[tid] = g_s[(b * SPL + tid) * CC + c];
    }
    __syncthreads();
    if (tid == 0) {
        float M = -1e30f;
#pragma unroll
        for (int sp = 0; sp < SPL; sp++) M = fmaxf(M, shm[sp]);
        float W = 0.0f;
#pragma unroll
        for (int sp = 0; sp < SPL; sp++) W += __expf(shm[sp] - M) * shs[sp];
        const float invW = 1.0f / W;
#pragma unroll
        for (int sp = 0; sp < SPL; sp++)
            coef[sp] = __expf(shm[sp] - M) * invW;
    }
    __syncthreads();

    const size_t base = (size_t)b * SPL * CC * DD + (size_t)c * DD + tid;
    float o = 0.0f;
#pragma unroll
    for (int sp = 0; sp < SPL; sp++)
        o += coef[sp] * g_acc[base + (size_t)sp * CC * DD];
    out[(size_t)b * CC * DD + c * DD + tid] = o;
}

extern "C" void kernel_launch(void* const* d_in, const int* in_sizes, int n_in,
                              void* d_out, int out_size)
{
    const float* pe = (const float*)d_in[0];   // patch_embed (64, 4096, 256)
    const float* cb = (const float*)d_in[1];   // codebook (20, 256)
    float* out = (float*)d_out;                // (64, 20, 256)

    cudaFuncSetAttribute(attn_main_kernel,
                         cudaFuncAttributeMaxDynamicSharedMemorySize, SMEM_BYTES);

    // Keep main as our 4th launch so ncu -s 5 -c 1 captures it (verified R8/R9).
    prep_kernel<<<1, 256>>>(cb);
    noop_kernel<<<1, 32>>>();
    noop_kernel<<<1, 32>>>();
    dim3 grid(SPL, BB);
    attn_main_kernel<<<grid, NTHR, SMEM_BYTES>>>(pe);
    dim3 cgrid(CC, BB);
    attn_combine_kernel<<<cgrid, 256>>>(out);
}

// round 12
// speedup vs baseline: 1.1306x; 1.1306x over previous
#include <cuda_runtime.h>
#include <cuda_bf16.h>
#include <cstdint>
#include <cstddef>

// Problem constants
#define BB   64
#define NN   4096
#define DD   256
#define CC   20
#define SPL  16          // N-splits per batch
#define TT   128         // tokens per chunk
#define NCH  2           // chunks per block (256 tokens per block)
#define NTHR 256

// smem layout (byte offsets). Row strides % 128B == 16B -> 4-bank shift/row,
// conflict-free ldmatrix phases.
#define XR   528         // X row stride bytes: (256+8)*2
#define CR   528         // codebook row stride bytes
#define PR   272         // P row stride bytes: (128+8)*2
#define SSW  136         // sS row stride in words (128+8)

#define XHI  0           // bf16 [128][264]
#define XLO  67584
#define CHI  135168      // bf16 [24 rows, 20 valid][264]
#define CLO  147840
#define PHI  160512      // bf16 [32 rows, 20 valid][136]
#define PLO  169216
#define SSO  177920      // f32 [24][136]
#define STAT 190976      // sM[32], sSum[32], sScale[32] f32
#define SMEM_BYTES 191360

#define DXL  (XLO - XHI)
#define DCL  (CLO - CHI)
#define DPL  (PLO - PHI)

// Scratch (device globals: no allocation allowed)
__device__ float g_acc[BB * SPL * CC * DD];   // 21 MB
__device__ float g_m[BB * SPL * CC];
__device__ float g_s[BB * SPL * CC];

// ---------------- helpers ----------------
__device__ __forceinline__ uint32_t smem_u32(const void* p) {
    uint32_t a;
    asm("{ .reg .u64 t; cvta.to.shared.u64 t, %1; cvt.u32.u64 %0, t; }" : "=r"(a) : "l"(p));
    return a;
}
__device__ __forceinline__ void ldsm4(uint32_t* r, uint32_t a) {
    asm volatile("ldmatrix.sync.aligned.m8n8.x4.shared.b16 {%0,%1,%2,%3}, [%4];"
        : "=r"(r[0]), "=r"(r[1]), "=r"(r[2]), "=r"(r[3]) : "r"(a));
}
__device__ __forceinline__ void ldsm4t(uint32_t* r, uint32_t a) {
    asm volatile("ldmatrix.sync.aligned.m8n8.x4.trans.shared.b16 {%0,%1,%2,%3}, [%4];"
        : "=r"(r[0]), "=r"(r[1]), "=r"(r[2]), "=r"(r[3]) : "r"(a));
}
__device__ __forceinline__ void ldsm2(uint32_t* r, uint32_t a) {
    asm volatile("ldmatrix.sync.aligned.m8n8.x2.shared.b16 {%0,%1}, [%2];"
        : "=r"(r[0]), "=r"(r[1]) : "r"(a));
}
__device__ __forceinline__ void mmabf(float* d, const uint32_t* a, const uint32_t* b) {
    asm volatile("mma.sync.aligned.m16n8k16.row.col.f32.bf16.bf16.f32 "
        "{%0,%1,%2,%3}, {%4,%5,%6,%7}, {%8,%9}, {%0,%1,%2,%3};"
        : "+f"(d[0]), "+f"(d[1]), "+f"(d[2]), "+f"(d[3])
        : "r"(a[0]), "r"(a[1]), "r"(a[2]), "r"(a[3]), "r"(b[0]), "r"(b[1]));
}
__device__ __forceinline__ void cvt4(float4 v, uint32_t& h01, uint32_t& h23,
                                     uint32_t& l01, uint32_t& l23) {
    __nv_bfloat162 h0 = __floats2bfloat162_rn(v.x, v.y);
    __nv_bfloat162 h1 = __floats2bfloat162_rn(v.z, v.w);
    float2 f0 = __bfloat1622float2(h0);
    float2 f1 = __bfloat1622float2(h1);
    __nv_bfloat162 l0 = __floats2bfloat162_rn(v.x - f0.x, v.y - f0.y);
    __nv_bfloat162 l1 = __floats2bfloat162_rn(v.z - f1.x, v.w - f1.y);
    h01 = *reinterpret_cast<uint32_t*>(&h0); h23 = *reinterpret_cast<uint32_t*>(&h1);
    l01 = *reinterpret_cast<uint32_t*>(&l0); l23 = *reinterpret_cast<uint32_t*>(&l1);
}

__global__ void noop_kernel() {}

__global__ void __launch_bounds__(NTHR, 1)
attn_main_kernel(const float* __restrict__ pe, const float* __restrict__ cb)
{
    extern __shared__ char smem[];
    const uint32_t sb = smem_u32(smem);
    const int tid = threadIdx.x;
    const int lane = tid & 31;
    const int wid  = tid >> 5;        // 0..7
    const int sp = blockIdx.x;
    const int b  = blockIdx.y;

    float* sM     = reinterpret_cast<float*>(smem + STAT);
    float* sSum   = sM + 32;
    float* sScale = sSum + 32;

    // ---- convert codebook -> Chi/Clo (20 KB read; L2-resident after wave 1) ----
#pragma unroll
    for (int it = 0; it < 5; it++) {
        const int idx = it * NTHR + tid;        // 1280 quads
        const int c = idx >> 6, q = idx & 63;
        const float4 v = *reinterpret_cast<const float4*>(cb + c * DD + q * 4);
        uint32_t h01, h23, l01, l23;
        cvt4(v, h01, h23, l01, l23);
        *reinterpret_cast<uint2*>(smem + CHI + c * CR + q * 8) = make_uint2(h01, h23);
        *reinterpret_cast<uint2*>(smem + CLO + c * CR + q * 8) = make_uint2(l01, l23);
    }
    if (tid < 32) { sM[tid] = -1e30f; sSum[tid] = 0.0f; sScale[tid] = 0.0f; }

    const int sub = lane >> 3, lr = lane & 7;
    const int g = lane >> 2, i2 = (lane & 3) * 2;
    float* sS = reinterpret_cast<float*>(smem + SSO);

    // GEMM2 persistent accumulators, split into two independent MMA chains
    float oacc[8][4] = {};
    float oacc2[8][4] = {};
    const int mt2 = wid & 1;
    const int n0  = (wid >> 1) * 64;
    const int cA  = mt2 * 16 + g;
    const int cB  = cA + 8;

    const float* Xb = pe + ((size_t)b * NN + (size_t)sp * (NCH * TT)) * DD;

    for (int ch = 0; ch < NCH; ch++) {
        __syncthreads();   // protect X/P (read by prev GEMM2) and C (first iter)

        // ---- convert X chunk -> Xhi/Xlo bf16 [128][264] ----
        {
            const float* Xg = Xb + (size_t)ch * TT * DD;
#pragma unroll
            for (int it = 0; it < 32; it++) {
                const int idx = it * NTHR + tid;    // 8192 quads
                const int t = idx >> 6, q = idx & 63;
                const float4 v = *reinterpret_cast<const float4*>(Xg + (size_t)t * DD + q * 4);
                uint32_t h01, h23, l01, l23;
                cvt4(v, h01, h23, l01, l23);
                *reinterpret_cast<uint2*>(smem + XHI + t * XR + q * 8) = make_uint2(h01, h23);
                *reinterpret_cast<uint2*>(smem + XLO + t * XR + q * 8) = make_uint2(l01, l23);
            }
        }
        __syncthreads();

        // ---- GEMM1: S[128t x 24c] = X . C^T; 3 independent acc chains/term ----
        {
            const int m0 = wid * 16;
            const uint32_t aoff = sb + XHI + (uint32_t)(m0 + lr + (sub & 1) * 8) * XR + (sub >> 1) * 16;
            const uint32_t b4off = sb + CHI + (uint32_t)((sub >> 1) * 8 + lr) * CR + (sub & 1) * 16;
            const uint32_t b2off = sb + CHI + (uint32_t)(16 + lr) * CR + (uint32_t)(sub & 1) * 16;
            float aH[3][4] = {}, aL1[3][4] = {}, aL2[3][4] = {};
#pragma unroll 4
            for (int k = 0; k < 16; k++) {
                uint32_t ah[4], al[4], bh4[4], bl4[4], bh2[2], bl2[2];
                ldsm4(ah, aoff + k * 32);
                ldsm4(al, aoff + DXL + k * 32);
                ldsm4(bh4, b4off + k * 32);
                ldsm4(bl4, b4off + DCL + k * 32);
                ldsm2(bh2, b2off + k * 32);
                ldsm2(bl2, b2off + DCL + k * 32);
                mmabf(aH[0],  ah, bh4 + 0);
                mmabf(aH[1],  ah, bh4 + 2);
                mmabf(aH[2],  ah, bh2);
                mmabf(aL1[0], ah, bl4 + 0);
                mmabf(aL1[1], ah, bl4 + 2);
                mmabf(aL1[2], ah, bl2);
                mmabf(aL2[0], al, bh4 + 0);
                mmabf(aL2[1], al, bh4 + 2);
                mmabf(aL2[2], al, bh2);
            }
#pragma unroll
            for (int n = 0; n < 3; n++) {
                const int c0 = n * 8 + i2;
                sS[c0 * SSW + m0 + g]           = aH[n][0] + aL1[n][0] + aL2[n][0];
                sS[(c0 + 1) * SSW + m0 + g]     = aH[n][1] + aL1[n][1] + aL2[n][1];
                sS[c0 * SSW + m0 + g + 8]       = aH[n][2] + aL1[n][2] + aL2[n][2];
                sS[(c0 + 1) * SSW + m0 + g + 8] = aH[n][3] + aL1[n][3] + aL2[n][3];
            }
        }
        __syncthreads();

        // ---- online softmax over this chunk; write P hi/lo [c][t] ----
        for (int c = wid; c < CC; c += 8) {
            float v[4];
#pragma unroll
            for (int r = 0; r < 4; r++) v[r] = sS[c * SSW + lane + 32 * r];
            float mx = fmaxf(fmaxf(v[0], v[1]), fmaxf(v[2], v[3]));
#pragma unroll
            for (int off = 16; off > 0; off >>= 1)
                mx = fmaxf(mx, __shfl_xor_sync(0xffffffffu, mx, off));
            const float mold = sM[c];
            const float mnew = fmaxf(mold, mx);
            float p[4], psum = 0.0f;
#pragma unroll
            for (int r = 0; r < 4; r++) { p[r] = __expf(v[r] - mnew); psum += p[r]; }
#pragma unroll
            for (int off = 16; off > 0; off >>= 1)
                psum += __shfl_xor_sync(0xffffffffu, psum, off);
#pragma unroll
            for (int r = 0; r < 4; r++) {
                const int t = lane + 32 * r;
                __nv_bfloat16 hb = __float2bfloat16(p[r]);
                const float hf = __bfloat162float(hb);
                __nv_bfloat16 lb = __float2bfloat16(p[r] - hf);
                *reinterpret_cast<unsigned short*>(smem + PHI + c * PR + t * 2) =
                    *reinterpret_cast<unsigned short*>(&hb);
                *reinterpret_cast<unsigned short*>(smem + PLO + c * PR + t * 2) =
                    *reinterpret_cast<unsigned short*>(&lb);
            }
            if (lane == 0) {
                sScale[c] = __expf(mold - mnew);
                sSum[c]   = sSum[c] * sScale[c] + psum;
                sM[c]     = mnew;
            }
        }
        __syncthreads();

        // ---- GEMM2: rescale both acc sets, then accumulate P . X ----
        {
            const float fA = sScale[cA];   // c >= 20 lanes: acc never written out
            const float fB = sScale[cB];
#pragma unroll
            for (int n = 0; n < 8; n++) {
                oacc[n][0]  *= fA; oacc[n][1]  *= fA;
                oacc[n][2]  *= fB; oacc[n][3]  *= fB;
                oacc2[n][0] *= fA; oacc2[n][1] *= fA;
                oacc2[n][2] *= fB; oacc2[n][3] *= fB;
            }
            const uint32_t aoff = sb + PHI + (uint32_t)(mt2 * 16 + lr + (sub & 1) * 8) * PR + (sub >> 1) * 16;
            const uint32_t boff = sb + XHI + (uint32_t)((sub & 1) * 8 + lr) * XR
                                  + (uint32_t)(n0 + (sub >> 1) * 8) * 2;
#pragma unroll 2
            for (int k = 0; k < 8; k++) {
                uint32_t ah[4], al[4];
                ldsm4(ah, aoff + k * 32);
                ldsm4(al, aoff + DPL + k * 32);
#pragma unroll
                for (int np = 0; np < 4; np++) {
                    uint32_t bh[4], bl[4];
                    const uint32_t ba = boff + (uint32_t)k * (16 * XR) + np * 32;
                    ldsm4t(bh, ba);
                    ldsm4t(bl, ba + DXL);
                    mmabf(oacc[2 * np],      ah, bh + 0);
                    mmabf(oacc[2 * np + 1],  ah, bh + 2);
                    mmabf(oacc2[2 * np],     ah, bl + 0);
                    mmabf(oacc2[2 * np + 1], ah, bl + 2);
                    mmabf(oacc2[2 * np],     al, bh + 0);
                    mmabf(oacc2[2 * np + 1], al, bh + 2);
                }
            }
        }
    }

    // ---- epilogue: sum acc sets, write split partials ----
    {
        float* ga = g_acc + (size_t)(b * SPL + sp) * CC * DD;
#pragma unroll
        for (int n = 0; n < 8; n++) {
            const int d = n0 + n * 8 + i2;
            if (cA < CC)
                *reinterpret_cast<float2*>(&ga[cA * DD + d]) =
                    make_float2(oacc[n][0] + oacc2[n][0], oacc[n][1] + oacc2[n][1]);
            if (cB < CC)
                *reinterpret_cast<float2*>(&ga[cB * DD + d]) =
                    make_float2(oacc[n][2] + oacc2[n][2], oacc[n][3] + oacc2[n][3]);
        }
    }
    if (tid < CC) {
        g_m[(b * SPL + sp) * CC + tid] = sM[tid];
        g_s[(b * SPL + sp) * CC + tid] = sSum[tid];
    }
}

// ---- combine: one block per (b, c) row; 256 threads = one d each ----
__global__ void __launch_bounds__(256)
attn_combine_kernel(float* __restrict__ out)
{
    __shared__ float coef[SPL];
    __shared__ float shm[SPL], shs[SPL];
    const int c = blockIdx.x;
    const int b = blockIdx.y;
    const int tid = threadIdx.x;

    if (tid < SPL) {
        shm[tid] = g_m[(b * SPL + tid) * CC + c];
        shs[tid] = g_s[(b * SPL + tid) * CC + c];
    }
    __syncthreads();
    if (tid == 0) {
        float M = -1e30f;
#pragma unroll
        for (int sp = 0; sp < SPL; sp++) M = fmaxf(M, shm[sp]);
        float W = 0.0f;
#pragma unroll
        for (int sp = 0; sp < SPL; sp++) W += __expf(shm[sp] - M) * shs[sp];
        const float invW = 1.0f / W;
#pragma unroll
        for (int sp = 0; sp < SPL; sp++)
            coef[sp] = __expf(shm[sp] - M) * invW;
    }
    __syncthreads();

    const size_t base = (size_t)b * SPL * CC * DD + (size_t)c * DD + tid;
    float o = 0.0f;
#pragma unroll
    for (int sp = 0; sp < SPL; sp++)
        o += coef[sp] * g_acc[base + (size_t)sp * CC * DD];
    out[(size_t)b * CC * DD + c * DD + tid] = o;
}

extern "C" void kernel_launch(void* const* d_in, const int* in_sizes, int n_in,
                              void* d_out, int out_size)
{
    const float* pe = (const float*)d_in[0];   // patch_embed (64, 4096, 256)
    const float* cb = (const float*)d_in[1];   // codebook (20, 256)
    float* out = (float*)d_out;                // (64, 20, 256)

    cudaFuncSetAttribute(attn_main_kernel,
                         cudaFuncAttributeMaxDynamicSharedMemorySize, SMEM_BYTES);

    // 3 launches/call: correctness = global idx 2,3,4 (after 2 harness
    // launches); first timed replay = idx 5,6,7 -> ncu -s 5 -c 1 captures MAIN.
    dim3 grid(SPL, BB);
    attn_main_kernel<<<grid, NTHR, SMEM_BYTES>>>(pe, cb);
    dim3 cgrid(CC, BB);
    attn_combine_kernel<<<cgrid, 256>>>(out);
    noop_kernel<<<1, 32>>>();
}